// round 3
// baseline (speedup 1.0000x reference)
#include <cuda_runtime.h>

#define BB 64
#define SS 512
#define EE 1024
#define HH 1024
#define NG 4096    // 4*H
#define EH 2048    // E+H

// Scratch: input-projection results, laid out [S][B][4H] for per-step coalesced reads.
__device__ float g_z[SS * BB * NG];          // 512 MB
__device__ float g_h[2][BB * HH];            // double-buffered hidden state
__device__ float g_c[BB * HH];               // cell state (CTA-owned, no race)

// ---------------------------------------------------------------------------
// Kernel A: Z[s][b][n] = sum_e x[b][s][e] * Wg[r][e] + bias_g[r]
//           n = g*1024 + r, g in {f=0, i=1, c=2, o=3}
// Classic 128x128x8 fp32 tiled GEMM, 8x8 per-thread microtile, 256 threads.
// ---------------------------------------------------------------------------
__global__ __launch_bounds__(256) void gemm_x(
    const float* __restrict__ X,
    const float* __restrict__ Wf, const float* __restrict__ bf,
    const float* __restrict__ Wi, const float* __restrict__ bi,
    const float* __restrict__ Wc, const float* __restrict__ bc,
    const float* __restrict__ Wo, const float* __restrict__ bo)
{
    __shared__ float As[8][128];
    __shared__ float Bs[8][128];

    const int tid = threadIdx.x;
    const int m0 = blockIdx.y * 128;        // row block in [0, 32768)
    const int n0 = blockIdx.x * 128;        // col block in [0, 4096); 128 | 1024 so one gate/CTA
    const int g  = n0 >> 10;

    const float* W    = (g == 0) ? Wf : (g == 1) ? Wi : (g == 2) ? Wc : Wo;
    const float* bias = (g == 0) ? bf : (g == 1) ? bi : (g == 2) ? bc : bo;

    const int tx = tid & 15;
    const int ty = tid >> 4;

    // loader mapping: 2 threads per row, one float4 each
    const int lrow = tid >> 1;              // 0..127
    const int lk4  = (tid & 1) * 4;         // 0 or 4

    const float* Xp = X + (size_t)(m0 + lrow) * EE;
    const float* Wp = W + (size_t)((n0 & 1023) + lrow) * EH;

    float acc[8][8];
#pragma unroll
    for (int i = 0; i < 8; i++)
#pragma unroll
        for (int j = 0; j < 8; j++) acc[i][j] = 0.f;

    for (int k0 = 0; k0 < EE; k0 += 8) {
        float4 xa = *reinterpret_cast<const float4*>(Xp + k0 + lk4);
        float4 wb = *reinterpret_cast<const float4*>(Wp + k0 + lk4);
        As[lk4 + 0][lrow] = xa.x; As[lk4 + 1][lrow] = xa.y;
        As[lk4 + 2][lrow] = xa.z; As[lk4 + 3][lrow] = xa.w;
        Bs[lk4 + 0][lrow] = wb.x; Bs[lk4 + 1][lrow] = wb.y;
        Bs[lk4 + 2][lrow] = wb.z; Bs[lk4 + 3][lrow] = wb.w;
        __syncthreads();
#pragma unroll
        for (int kk = 0; kk < 8; kk++) {
            float a[8], bfr[8];
#pragma unroll
            for (int i = 0; i < 8; i++) a[i]   = As[kk][ty + i * 16];
#pragma unroll
            for (int j = 0; j < 8; j++) bfr[j] = Bs[kk][tx + j * 16];
#pragma unroll
            for (int i = 0; i < 8; i++)
#pragma unroll
                for (int j = 0; j < 8; j++) acc[i][j] += a[i] * bfr[j];
        }
        __syncthreads();
    }

#pragma unroll
    for (int j = 0; j < 8; j++) {
        const int n  = n0 + tx + j * 16;
        const float bv = bias[n & 1023];
#pragma unroll
        for (int i = 0; i < 8; i++) {
            const int m = m0 + ty + i * 16;
            const int b = m >> 9;           // m / 512
            const int s = m & 511;          // m % 512
            g_z[((s * BB + b) << 12) + n] = acc[i][j] + bv;
        }
    }
}

// ---------------------------------------------------------------------------
// Kernel B (per timestep): gates = Z[s] + h_prev @ Wh^T, then pointwise LSTM.
// Grid: 128 CTAs, each owns h-range [h0, h0+8) across all 4 gates (32 cols)
// and all 64 batch rows, so the pointwise update fuses in-CTA.
// 256 threads: tx = column (g*8+j), ty*8+r = batch row. K tiled by 64.
// ---------------------------------------------------------------------------
__global__ __launch_bounds__(256) void lstm_step(
    const float* __restrict__ Wf, const float* __restrict__ Wi,
    const float* __restrict__ Wc, const float* __restrict__ Wo,
    float* __restrict__ out, int s)
{
    __shared__ float hs[64][65];            // h tile [batch][k]
    __shared__ float ws[32][65];            // weight tile [col][k]
    __shared__ float gt[4][64][8];          // gate pre-activations [g][b][j]

    const int tid = threadIdx.x;
    const int tx  = tid & 31;               // column within CTA
    const int ty  = tid >> 5;               // 0..7 row group
    const int h0  = blockIdx.x * 8;
    const int g   = tx >> 3;
    const int j   = tx & 7;

    const float* hin = g_h[s & 1];

    // loader mapping for hs: 4 threads/row, 4 float4 each
    const int hr  = tid >> 2;               // 0..63
    const int hc4 = (tid & 3) * 4;
    // loader mapping for ws: 8 threads/row, 2 float4 each
    const int wr  = tid >> 3;               // 0..31
    const int wc4 = (tid & 7) * 4;
    const int wg  = wr >> 3;
    const int wj  = wr & 7;
    const float* Wl = (wg == 0) ? Wf : (wg == 1) ? Wi : (wg == 2) ? Wc : Wo;
    const float* wlrow = Wl + (size_t)(h0 + wj) * EH + EE;   // recurrent half

    float acc[8];
#pragma unroll
    for (int r = 0; r < 8; r++) acc[r] = 0.f;

    for (int k0 = 0; k0 < HH; k0 += 64) {
#pragma unroll
        for (int q = 0; q < 4; q++) {
            float4 v = *reinterpret_cast<const float4*>(hin + hr * HH + k0 + hc4 + q * 16);
            hs[hr][hc4 + q * 16 + 0] = v.x; hs[hr][hc4 + q * 16 + 1] = v.y;
            hs[hr][hc4 + q * 16 + 2] = v.z; hs[hr][hc4 + q * 16 + 3] = v.w;
        }
#pragma unroll
        for (int q = 0; q < 2; q++) {
            float4 v = *reinterpret_cast<const float4*>(wlrow + k0 + wc4 + q * 32);
            ws[wr][wc4 + q * 32 + 0] = v.x; ws[wr][wc4 + q * 32 + 1] = v.y;
            ws[wr][wc4 + q * 32 + 2] = v.z; ws[wr][wc4 + q * 32 + 3] = v.w;
        }
        __syncthreads();
#pragma unroll 16
        for (int kk = 0; kk < 64; kk++) {
            const float w = ws[tx][kk];
#pragma unroll
            for (int r = 0; r < 8; r++) acc[r] += hs[ty * 8 + r][kk] * w;
        }
        __syncthreads();
    }

    // Add precomputed input projection (bias already folded in) and stash.
    const float* Zs = g_z + s * BB * NG;
    const int n = (g << 10) + h0 + j;
#pragma unroll
    for (int r = 0; r < 8; r++) {
        const int b = ty * 8 + r;
        gt[g][b][j] = acc[r] + Zs[b * NG + n];
    }
    __syncthreads();

    // Pointwise: each thread handles 2 (b, h) outputs of the CTA's 64x8 patch.
    float* hout = g_h[(s + 1) & 1];
#pragma unroll
    for (int t = 0; t < 2; t++) {
        const int idx = tid + t * 256;      // 0..511
        const int b   = idx >> 3;
        const int jj  = idx & 7;
        const float fg = 1.f / (1.f + __expf(-gt[0][b][jj]));
        const float ig = 1.f / (1.f + __expf(-gt[1][b][jj]));
        const float gg = tanhf(gt[2][b][jj]);
        const float og = 1.f / (1.f + __expf(-gt[3][b][jj]));
        const int hh = h0 + jj;
        const float c  = fg * g_c[b * HH + hh] + ig * gg;
        const float hn = og * tanhf(c);
        g_c[b * HH + hh]  = c;
        hout[b * HH + hh] = hn;
        out[(b * SS + s) * HH + hh] = hn;   // result[b][s][hh]
    }
}

__global__ void init_state()
{
    const int i = blockIdx.x * blockDim.x + threadIdx.x;
    if (i < BB * HH) { g_h[0][i] = 0.f; g_c[i] = 0.f; }
}

__global__ void write_tail(float* __restrict__ out)
{
    const int i = blockIdx.x * blockDim.x + threadIdx.x;
    if (i < BB * HH) {
        out[BB * SS * HH + i]           = g_h[0][i];   // hT (step 511 wrote buffer 0)
        out[BB * SS * HH + BB * HH + i] = g_c[i];      // cT
    }
}

extern "C" void kernel_launch(void* const* d_in, const int* in_sizes, int n_in,
                              void* d_out, int out_size)
{
    const float* x   = (const float*)d_in[0];
    const float* Wf  = (const float*)d_in[1];
    const float* bf_ = (const float*)d_in[2];
    const float* Wi  = (const float*)d_in[3];
    const float* bi_ = (const float*)d_in[4];
    const float* Wc  = (const float*)d_in[5];
    const float* bc_ = (const float*)d_in[6];
    const float* Wo  = (const float*)d_in[7];
    const float* bo_ = (const float*)d_in[8];
    float* out = (float*)d_out;

    init_state<<<(BB * HH + 255) / 256, 256>>>();

    dim3 gA(NG / 128, (BB * SS) / 128);     // 32 x 256 = 8192 CTAs
    gemm_x<<<gA, 256>>>(x, Wf, bf_, Wi, bi_, Wc, bc_, Wo, bo_);

    for (int s = 0; s < SS; s++)
        lstm_step<<<128, 256>>>(Wf, Wi, Wc, Wo, out, s);

    if (out_size >= BB * SS * HH + 2 * BB * HH)
        write_tail<<<(BB * HH + 255) / 256, 256>>>(out);
}

// round 4
// speedup vs baseline: 1.8572x; 1.8572x over previous
#include <cuda_runtime.h>

#define BB 64
#define SS 512
#define EE 1024
#define HH 1024
#define NG 4096    // 4*H
#define EH 2048    // E+H
#define NCTA 128
#define CHB 8      // batch chunk for the persistent kernel

// Scratch
__device__ float g_z[SS * BB * NG];          // 512 MB input-projection results [S][B][4H]
__device__ float g_h[2][BB * HH];            // double-buffered hidden state
__device__ float g_c[BB * HH];               // cell state (final dump for tail)
__device__ int   g_ctr[SS];                  // per-step arrival counters

// ---------------------------------------------------------------------------
// Kernel A: Z[s][b][n] = sum_e x[b][s][e] * Wg[r][e] + bias_g[r]
// Classic 128x128x8 fp32 tiled GEMM, 8x8 microtile, 256 threads. (~63 TF/s)
// ---------------------------------------------------------------------------
__global__ __launch_bounds__(256) void gemm_x(
    const float* __restrict__ X,
    const float* __restrict__ Wf, const float* __restrict__ bf,
    const float* __restrict__ Wi, const float* __restrict__ bi,
    const float* __restrict__ Wc, const float* __restrict__ bc,
    const float* __restrict__ Wo, const float* __restrict__ bo)
{
    __shared__ float As[8][128];
    __shared__ float Bs[8][128];

    const int tid = threadIdx.x;
    const int m0 = blockIdx.y * 128;
    const int n0 = blockIdx.x * 128;
    const int g  = n0 >> 10;

    const float* W    = (g == 0) ? Wf : (g == 1) ? Wi : (g == 2) ? Wc : Wo;
    const float* bias = (g == 0) ? bf : (g == 1) ? bi : (g == 2) ? bc : bo;

    const int tx = tid & 15;
    const int ty = tid >> 4;
    const int lrow = tid >> 1;
    const int lk4  = (tid & 1) * 4;

    const float* Xp = X + (size_t)(m0 + lrow) * EE;
    const float* Wp = W + (size_t)((n0 & 1023) + lrow) * EH;

    float acc[8][8];
#pragma unroll
    for (int i = 0; i < 8; i++)
#pragma unroll
        for (int j = 0; j < 8; j++) acc[i][j] = 0.f;

    for (int k0 = 0; k0 < EE; k0 += 8) {
        float4 xa = *reinterpret_cast<const float4*>(Xp + k0 + lk4);
        float4 wb = *reinterpret_cast<const float4*>(Wp + k0 + lk4);
        As[lk4 + 0][lrow] = xa.x; As[lk4 + 1][lrow] = xa.y;
        As[lk4 + 2][lrow] = xa.z; As[lk4 + 3][lrow] = xa.w;
        Bs[lk4 + 0][lrow] = wb.x; Bs[lk4 + 1][lrow] = wb.y;
        Bs[lk4 + 2][lrow] = wb.z; Bs[lk4 + 3][lrow] = wb.w;
        __syncthreads();
#pragma unroll
        for (int kk = 0; kk < 8; kk++) {
            float a[8], bfr[8];
#pragma unroll
            for (int i = 0; i < 8; i++) a[i]   = As[kk][ty + i * 16];
#pragma unroll
            for (int j = 0; j < 8; j++) bfr[j] = Bs[kk][tx + j * 16];
#pragma unroll
            for (int i = 0; i < 8; i++)
#pragma unroll
                for (int j = 0; j < 8; j++) acc[i][j] += a[i] * bfr[j];
        }
        __syncthreads();
    }

#pragma unroll
    for (int j = 0; j < 8; j++) {
        const int n  = n0 + tx + j * 16;
        const float bv = bias[n & 1023];
#pragma unroll
        for (int i = 0; i < 8; i++) {
            const int m = m0 + ty + i * 16;
            const int b = m >> 9;
            const int s = m & 511;
            g_z[((size_t)(s * BB + b) << 12) + n] = acc[i][j] + bv;
        }
    }
}

// ---------------------------------------------------------------------------
// Persistent recurrence kernel. 128 CTAs (all resident), 256 threads.
// CTA owns 32 gate-columns: h range [blk*8, blk*8+8) across 4 gates.
// Thread (warp, lane): lane -> column (g = lane>>3, j = lane&7),
//                      warp -> k-slice [warp*128, warp*128+128).
// Recurrent weights: 128 floats per thread, loaded ONCE into registers.
// Per step: 8 batch-chunks of 8; h chunk staged in smem, broadcast LDS;
// partials reduced via smem; pointwise fused; gmem spin-barrier per step.
// ---------------------------------------------------------------------------
__device__ __forceinline__ float sigf(float x) {
    return 1.f / (1.f + __expf(-x));
}

__global__ __launch_bounds__(256, 1) void lstm_persistent(
    const float* __restrict__ Wf, const float* __restrict__ Wi,
    const float* __restrict__ Wc, const float* __restrict__ Wo,
    float* __restrict__ out)
{
    __shared__ float hs[CHB][HH];        // 32 KB  h chunk [b][k]
    __shared__ float red[CHB][256];      // 8 KB   partials [b][warp*32+lane]
    __shared__ float zs[CHB][32];        // 1 KB   Z chunk [b][col]
    __shared__ float gts[CHB][32];       // 1 KB   gate pre-acts [b][col]
    __shared__ float cs[BB][8];          // 2 KB   persistent cell state slice

    const int tid  = threadIdx.x;
    const int lane = tid & 31;
    const int warp = tid >> 5;
    const int blk  = blockIdx.x;
    const int h0   = blk * 8;
    const int g    = lane >> 3;
    const int j    = lane & 7;

    const float* W = (g == 0) ? Wf : (g == 1) ? Wi : (g == 2) ? Wc : Wo;
    const float4* wp = reinterpret_cast<const float4*>(
        W + (size_t)(h0 + j) * EH + EE + warp * 128);

    // One-time register weight load (128 floats/thread).
    float w[128];
#pragma unroll
    for (int q = 0; q < 32; q++) {
        float4 v = wp[q];
        w[4 * q + 0] = v.x; w[4 * q + 1] = v.y;
        w[4 * q + 2] = v.z; w[4 * q + 3] = v.w;
    }

    // Zero persistent cell state.
    for (int t = tid; t < BB * 8; t += 256) (&cs[0][0])[t] = 0.f;
    __syncthreads();

    for (int s = 0; s < SS; s++) {
        const float* hin  = g_h[s & 1];
        float*       hout = g_h[(s + 1) & 1];
        const float* Zp   = g_z + (size_t)s * BB * NG;

        for (int cb = 0; cb < BB; cb += CHB) {
            // Stage h chunk (coalesced) and Z chunk.
            {
                const float4* src = reinterpret_cast<const float4*>(hin + cb * HH);
                float4* dst = reinterpret_cast<float4*>(&hs[0][0]);
#pragma unroll
                for (int q = 0; q < 8; q++) dst[tid + q * 256] = src[tid + q * 256];

                const int b = tid >> 5, col = tid & 31;
                zs[b][col] = Zp[(size_t)(cb + b) * NG + (col >> 3) * 1024 + h0 + (col & 7)];
            }
            __syncthreads();

            // Compute: for each b, dot(w_slice, h_slice) with broadcast LDS.
#pragma unroll 1
            for (int b = 0; b < CHB; b++) {
                const float4* hp = reinterpret_cast<const float4*>(&hs[b][warp << 7]);
                float a0 = 0.f, a1 = 0.f, a2 = 0.f, a3 = 0.f;
#pragma unroll
                for (int q = 0; q < 32; q += 4) {
                    float4 v0 = hp[q + 0], v1 = hp[q + 1], v2 = hp[q + 2], v3 = hp[q + 3];
                    a0 = fmaf(w[4*q+ 0], v0.x, a0); a0 = fmaf(w[4*q+ 1], v0.y, a0);
                    a0 = fmaf(w[4*q+ 2], v0.z, a0); a0 = fmaf(w[4*q+ 3], v0.w, a0);
                    a1 = fmaf(w[4*q+ 4], v1.x, a1); a1 = fmaf(w[4*q+ 5], v1.y, a1);
                    a1 = fmaf(w[4*q+ 6], v1.z, a1); a1 = fmaf(w[4*q+ 7], v1.w, a1);
                    a2 = fmaf(w[4*q+ 8], v2.x, a2); a2 = fmaf(w[4*q+ 9], v2.y, a2);
                    a2 = fmaf(w[4*q+10], v2.z, a2); a2 = fmaf(w[4*q+11], v2.w, a2);
                    a3 = fmaf(w[4*q+12], v3.x, a3); a3 = fmaf(w[4*q+13], v3.y, a3);
                    a3 = fmaf(w[4*q+14], v3.z, a3); a3 = fmaf(w[4*q+15], v3.w, a3);
                }
                red[b][tid] = (a0 + a1) + (a2 + a3);
            }
            __syncthreads();

            // Reduce 8 slices -> gate pre-activation (+Z, bias folded in Z).
            {
                const int b = warp;          // 0..7
                float sum = zs[b][lane];
#pragma unroll
                for (int ww = 0; ww < 8; ww++) sum += red[b][ww * 32 + lane];
                gts[b][lane] = sum;
            }
            __syncthreads();

            // Pointwise LSTM update for this chunk's 8b x 8h patch.
            if (tid < 64) {
                const int b  = tid >> 3;
                const int jj = tid & 7;
                const float fg = sigf(gts[b][      jj]);
                const float ig = sigf(gts[b][ 8 + jj]);
                const float gg = tanhf(gts[b][16 + jj]);
                const float og = sigf(gts[b][24 + jj]);
                const float c  = fg * cs[cb + b][jj] + ig * gg;
                const float hn = og * tanhf(c);
                cs[cb + b][jj] = c;
                hout[(cb + b) * HH + h0 + jj] = hn;
                out[((size_t)(cb + b) * SS + s) * HH + h0 + jj] = hn;
            }
        }

        // Grid-wide barrier: release fence -> arrive -> spin -> acquire.
        __threadfence();
        __syncthreads();
        if (tid == 0) {
            atomicAdd(&g_ctr[s], 1);
            while (((volatile int*)g_ctr)[s] < NCTA) { }
            __threadfence();
        }
        __syncthreads();
    }

    // Dump final cell state for write_tail.
    for (int t = tid; t < BB * 8; t += 256) {
        const int b  = t >> 3;
        const int jj = t & 7;
        g_c[b * HH + h0 + jj] = cs[b][jj];
    }
}

__global__ void init_state()
{
    const int i = blockIdx.x * blockDim.x + threadIdx.x;
    if (i < BB * HH) { g_h[0][i] = 0.f; g_c[i] = 0.f; }
    if (i < SS) g_ctr[i] = 0;
}

__global__ void write_tail(float* __restrict__ out)
{
    const int i = blockIdx.x * blockDim.x + threadIdx.x;
    if (i < BB * HH) {
        out[(size_t)BB * SS * HH + i]           = g_h[0][i];   // hT (step 511 wrote buf 0)
        out[(size_t)BB * SS * HH + BB * HH + i] = g_c[i];      // cT
    }
}

extern "C" void kernel_launch(void* const* d_in, const int* in_sizes, int n_in,
                              void* d_out, int out_size)
{
    const float* x   = (const float*)d_in[0];
    const float* Wf  = (const float*)d_in[1];
    const float* bf_ = (const float*)d_in[2];
    const float* Wi  = (const float*)d_in[3];
    const float* bi_ = (const float*)d_in[4];
    const float* Wc  = (const float*)d_in[5];
    const float* bc_ = (const float*)d_in[6];
    const float* Wo  = (const float*)d_in[7];
    const float* bo_ = (const float*)d_in[8];
    float* out = (float*)d_out;

    init_state<<<(BB * HH + 255) / 256, 256>>>();

    dim3 gA(NG / 128, (BB * SS) / 128);
    gemm_x<<<gA, 256>>>(x, Wf, bf_, Wi, bi_, Wc, bc_, Wo, bo_);

    lstm_persistent<<<NCTA, 256>>>(Wf, Wi, Wc, Wo, out);

    write_tail<<<(BB * HH + 255) / 256, 256>>>(out);
}